// round 6
// baseline (speedup 1.0000x reference)
#include <cuda_runtime.h>
#include <cuda_fp16.h>
#include <mma.h>
#include <cstdint>
#include <math.h>

using namespace nvcuda;

#define BB 2
#define NN 2048
#define CC 1024
#define HH 16
#define DD 64
#define INNER 1024
#define QK_SCALE 0.125f

// fp16 hi/lo split scratch
__device__ __half g_xh[4194304],  g_xl[4194304];
__device__ __half g_wqh[3145728], g_wql[3145728];
__device__ __half g_wph[1048576], g_wpl[1048576];
__device__ __half g_qkvh[12582912], g_qkvl[12582912];
__device__ __half g_ath[4194304], g_atl[4194304];

// ---------------------------------------------------------------------------
__device__ __forceinline__ uint32_t smem_u32(const void* p) {
    uint32_t a;
    asm("{ .reg .u64 t; cvta.to.shared.u64 t, %1; cvt.u32.u64 %0, t; }"
        : "=r"(a) : "l"(p));
    return a;
}
__device__ __forceinline__ void cp16(uint32_t dst, const void* src) {
    asm volatile("cp.async.cg.shared.global [%0], [%1], 16;"
                 :: "r"(dst), "l"(src));
}
#define CP_COMMIT() asm volatile("cp.async.commit_group;" ::: "memory")
#define CP_WAIT1()  asm volatile("cp.async.wait_group 1;" ::: "memory")
#define CP_WAIT0()  asm volatile("cp.async.wait_group 0;" ::: "memory")

#define LDSM_X4(r0,r1,r2,r3,addr) \
    asm volatile("ldmatrix.sync.aligned.m8n8.x4.shared.b16 {%0,%1,%2,%3}, [%4];" \
        : "=r"(r0),"=r"(r1),"=r"(r2),"=r"(r3) : "r"(addr))
#define LDSM_X4T(r0,r1,r2,r3,addr) \
    asm volatile("ldmatrix.sync.aligned.m8n8.x4.trans.shared.b16 {%0,%1,%2,%3}, [%4];" \
        : "=r"(r0),"=r"(r1),"=r"(r2),"=r"(r3) : "r"(addr))
#define MMA16816(c,a,b0,b1) \
    asm volatile("mma.sync.aligned.m16n8k16.row.col.f32.f16.f16.f32 " \
        "{%0,%1,%2,%3},{%4,%5,%6,%7},{%8,%9},{%0,%1,%2,%3};" \
        : "+f"((c)[0]),"+f"((c)[1]),"+f"((c)[2]),"+f"((c)[3]) \
        : "r"((a)[0]),"r"((a)[1]),"r"((a)[2]),"r"((a)[3]),"r"(b0),"r"(b1))

__device__ __forceinline__ uint32_t pk2(float lo, float hi) {
    uint32_t u;
    asm("cvt.rn.f16x2.f32 %0, %1, %2;" : "=r"(u) : "f"(hi), "f"(lo));
    return u;
}
__device__ __forceinline__ void split1(float v, __half& h, __half& l) {
    h = __float2half_rn(v);
    l = __float2half_rn(v - __half2float(h));
}

typedef wmma::fragment<wmma::matrix_a, 16, 16, 16, __half, wmma::row_major> HA;
typedef wmma::fragment<wmma::matrix_b, 16, 16, 16, __half, wmma::row_major> HBr;
typedef wmma::fragment<wmma::accumulator, 16, 16, 16, float> HC;

// ---------------------------------------------------------------------------
// Merged pre-split kernel: all 3 fp32 inputs -> (hi, lo) fp16 in one launch.
// Region sizes in float4: x 1048576, w_qkv 786432, w_proj 262144.
// ---------------------------------------------------------------------------
__global__ __launch_bounds__(256) void splitall(
    const float* __restrict__ x, const float* __restrict__ wq,
    const float* __restrict__ wp)
{
    int i = blockIdx.x * 256 + threadIdx.x;
    const float4* s;
    __half2 *hi, *lo;
    int j;
    if (i < 1048576) {
        s = (const float4*)x;  hi = (__half2*)g_xh;  lo = (__half2*)g_xl;  j = i;
    } else if (i < 1835008) {
        s = (const float4*)wq; hi = (__half2*)g_wqh; lo = (__half2*)g_wql; j = i - 1048576;
    } else {
        s = (const float4*)wp; hi = (__half2*)g_wph; lo = (__half2*)g_wpl; j = i - 1835008;
    }
    float4 v = s[j];
    __half h0, h1, h2, h3, l0, l1, l2, l3;
    split1(v.x, h0, l0); split1(v.y, h1, l1);
    split1(v.z, h2, l2); split1(v.w, h3, l3);
    hi[2 * j]     = __halves2half2(h0, h1);
    hi[2 * j + 1] = __halves2half2(h2, h3);
    lo[2 * j]     = __halves2half2(l0, l1);
    lo[2 * j + 1] = __halves2half2(l2, l3);
}

// ---------------------------------------------------------------------------
// fp16 split GEMM (wmma): 128x128 tile, 256 thr, K-step 32,
// 3-stage cp.async pipeline, ONE barrier per k-tile.
// ---------------------------------------------------------------------------
#define GP_A 40
#define GP_B 136
#define A_HALF (128 * GP_A)
#define B_HALF (32 * GP_B)
#define G_ABYTES (A_HALF * 2)
#define G_BBYTES (B_HALF * 2)
#define G_STAGE (2 * G_ABYTES + 2 * G_BBYTES)   // 37888
#define G_SMEM (3 * G_STAGE)                    // 113664

__device__ __forceinline__ void g_issue(
    uint32_t sb, const __half* Ah, const __half* Al,
    const __half* Bh, const __half* Bl,
    int m0, int n0, int K, int N, int kt, int buf, int tid)
{
    uint32_t st = sb + (uint32_t)buf * G_STAGE;
#pragma unroll
    for (int i = 0; i < 4; i++) {
        int idx = tid + i * 256;
        int arr = idx >> 9, e = idx & 511;
        int r = e >> 2, f = e & 3;
        const __half* src = (arr ? Al : Ah) + (size_t)(m0 + r) * K + kt * 32 + f * 8;
        cp16(st + (uint32_t)arr * G_ABYTES + (uint32_t)(r * GP_A + f * 8) * 2, src);
    }
#pragma unroll
    for (int i = 0; i < 4; i++) {
        int idx = tid + i * 256;
        int arr = idx >> 9, e = idx & 511;
        int r = e >> 4, f = e & 15;
        const __half* src = (arr ? Bl : Bh) + (size_t)(kt * 32 + r) * N + n0 + f * 8;
        cp16(st + 2 * G_ABYTES + (uint32_t)arr * G_BBYTES
                + (uint32_t)(r * GP_B + f * 8) * 2, src);
    }
}

__global__ __launch_bounds__(256, 2) void gemm_h(
    const __half* __restrict__ Ah, const __half* __restrict__ Al,
    const __half* __restrict__ Bh, const __half* __restrict__ Bl,
    float* __restrict__ Cout, const float* __restrict__ bias,
    __half* __restrict__ Ch, __half* __restrict__ Cl,
    int M, int N, int K, int mode)
{
    extern __shared__ char sm[];
    const uint32_t sb = smem_u32(sm);
    const int tid = threadIdx.x;
    const int wid = tid >> 5;
    const int wm = wid & 3;
    const int wn = wid >> 2;
    const int m0 = blockIdx.y * 128;
    const int n0 = blockIdx.x * 128;

    HC acc[2][4];
#pragma unroll
    for (int i = 0; i < 2; i++)
#pragma unroll
        for (int j = 0; j < 4; j++) wmma::fill_fragment(acc[i][j], 0.0f);

    const int nkt = K / 32;
    g_issue(sb, Ah, Al, Bh, Bl, m0, n0, K, N, 0, 0, tid); CP_COMMIT();
    g_issue(sb, Ah, Al, Bh, Bl, m0, n0, K, N, 1, 1, tid); CP_COMMIT();

    for (int kt = 0; kt < nkt; kt++) {
        CP_WAIT1();
        __syncthreads();
        if (kt + 2 < nkt) {
            g_issue(sb, Ah, Al, Bh, Bl, m0, n0, K, N, kt + 2, (kt + 2) % 3, tid);
            CP_COMMIT();
        }
        const __half* st  = (const __half*)(sm + (size_t)(kt % 3) * G_STAGE);
        const __half* Ash = st;
        const __half* Asl = st + A_HALF;
        const __half* Bsh = st + 2 * A_HALF;
        const __half* Bsl = st + 2 * A_HALF + B_HALF;

#pragma unroll
        for (int s = 0; s < 2; s++) {
            HA ah[2], al[2];
#pragma unroll
            for (int i = 0; i < 2; i++) {
                wmma::load_matrix_sync(ah[i], Ash + (wm * 32 + i * 16) * GP_A + s * 16, GP_A);
                wmma::load_matrix_sync(al[i], Asl + (wm * 32 + i * 16) * GP_A + s * 16, GP_A);
            }
#pragma unroll
            for (int j = 0; j < 4; j++) {
                HBr bh, bl;
                wmma::load_matrix_sync(bh, Bsh + (s * 16) * GP_B + wn * 64 + j * 16, GP_B);
                wmma::load_matrix_sync(bl, Bsl + (s * 16) * GP_B + wn * 64 + j * 16, GP_B);
#pragma unroll
                for (int i = 0; i < 2; i++) {
                    wmma::mma_sync(acc[i][j], ah[i], bh, acc[i][j]);
                    wmma::mma_sync(acc[i][j], ah[i], bl, acc[i][j]);
                    wmma::mma_sync(acc[i][j], al[i], bh, acc[i][j]);
                }
            }
        }
    }
    CP_WAIT0();
    __syncthreads();

    float* Cs = (float*)sm;
#pragma unroll
    for (int i = 0; i < 2; i++)
#pragma unroll
        for (int j = 0; j < 4; j++)
            wmma::store_matrix_sync(Cs + (wm * 32 + i * 16) * 128 + wn * 64 + j * 16,
                                    acc[i][j], 128, wmma::mem_row_major);
    __syncthreads();
#pragma unroll
    for (int i = 0; i < 16; i++) {
        int idx = tid + i * 256;
        int r = idx >> 5, f = idx & 31;
        float4 v = *(float4*)(Cs + r * 128 + f * 4);
        int gc = n0 + f * 4;
        if (mode == 1) {
            const float* bp = bias + gc;
            v.x += bp[0]; v.y += bp[1]; v.z += bp[2]; v.w += bp[3];
            *(float4*)(Cout + (size_t)(m0 + r) * N + gc) = v;
        } else {
            float sc = (gc < 1024) ? QK_SCALE : 1.0f;
            v.x *= sc; v.y *= sc; v.z *= sc; v.w *= sc;
            __half h0, h1, h2, h3, l0, l1, l2, l3;
            split1(v.x, h0, l0); split1(v.y, h1, l1);
            split1(v.z, h2, l2); split1(v.w, h3, l3);
            __half2* ph = (__half2*)(Ch + (size_t)(m0 + r) * N + gc);
            __half2* pl = (__half2*)(Cl + (size_t)(m0 + r) * N + gc);
            ph[0] = __halves2half2(h0, h1); ph[1] = __halves2half2(h2, h3);
            pl[0] = __halves2half2(l0, l1); pl[1] = __halves2half2(l2, l3);
        }
    }
}

// ---------------------------------------------------------------------------
// Flash attention, register-resident mma.sync, triple-buffered K/V,
// ldmatrix.x4 (two n8 blocks per load). One barrier per iteration.
// ---------------------------------------------------------------------------
#define FPK 72                     // smem pitch in halves
#define KV_TILE 4608               // 64*72 halves per tile
#define KV_BUF 18432               // 4 tiles (Kh,Kl,Vh,Vl) in halves
#define F_SMEM (3 * KV_BUF * 2)    // 110592 bytes
#define Q_OFF (2 * KV_BUF)         // Q staged in buf2 (halves offset)

__device__ __forceinline__ void kv_issue(uint32_t sb, int b, int h, int kt,
                                         int buf, int tid)
{
    size_t rowbase = (size_t)(b * NN + kt * 64) * 3072 + 1024 + h * 64;
#pragma unroll
    for (int i = 0; i < 8; i++) {
        int idx = tid + i * 256;
        int arr = idx >> 9;           // 0:Kh 1:Kl 2:Vh 3:Vl
        int e = idx & 511;
        int r = e >> 3, f = e & 7;
        const __half* src = ((arr & 1) ? g_qkvl : g_qkvh)
            + rowbase + (size_t)(arr >> 1) * 1024 + (size_t)r * 3072 + f * 8;
        uint32_t dst = sb + (uint32_t)(buf * KV_BUF + arr * KV_TILE + r * FPK + f * 8) * 2;
        cp16(dst, src);
    }
}

__global__ __launch_bounds__(256, 2) void flash_r()
{
    extern __shared__ char sm[];
    const uint32_t sb = smem_u32(sm);
    const int tid = threadIdx.x;
    const int w = tid >> 5;
    const int lane = tid & 31;
    const int l15 = lane & 15;
    const int g = lane >> 2;
    const int tg = lane & 3;
    const int b = blockIdx.y >> 4;
    const int h = blockIdx.y & 15;
    const int q0 = blockIdx.x * 128;

    // ---- prologue: stage Q (buf2) + KV(0) as group A, KV(1) as group B ----
    {
        size_t qrowbase = (size_t)(b * NN + q0) * 3072 + h * 64;
#pragma unroll
        for (int i = 0; i < 8; i++) {
            int idx = tid + i * 256;
            int arr = idx >> 10;          // 0: Qh, 1: Ql
            int e = idx & 1023;
            int r = e >> 3, f = e & 7;
            const __half* src = (arr ? g_qkvl : g_qkvh)
                + qrowbase + (size_t)r * 3072 + f * 8;
            uint32_t dst = sb + (uint32_t)(Q_OFF + arr * 9216 + r * FPK + f * 8) * 2;
            cp16(dst, src);
        }
    }
    kv_issue(sb, b, h, 0, 0, tid);
    CP_COMMIT();
    kv_issue(sb, b, h, 1, 1, tid);
    CP_COMMIT();
    CP_WAIT1();          // group A (Q + KV0) landed
    __syncthreads();

    uint32_t qh[4][4], ql[4][4];
    {
        uint32_t qrow = (uint32_t)(w * 16 + l15);
#pragma unroll
        for (int t = 0; t < 4; t++) {
            uint32_t a = sb + (uint32_t)(Q_OFF + qrow * FPK + t * 16 + (lane >> 4) * 8) * 2;
            LDSM_X4(qh[t][0], qh[t][1], qh[t][2], qh[t][3], a);
            LDSM_X4(ql[t][0], ql[t][1], ql[t][2], ql[t][3], a + 9216 * 2);
        }
    }
    // buf2 (Q region) overwritten first at iter 0's issue of KV(2);
    // protected by the loop's top barrier.

    float o[8][4];
#pragma unroll
    for (int j = 0; j < 8; j++)
#pragma unroll
        for (int e = 0; e < 4; e++) o[j][e] = 0.0f;
    float m0 = -INFINITY, m1 = -INFINITY, ls0 = 0.0f, ls1 = 0.0f;

    for (int kt = 0; kt < 32; kt++) {
        CP_WAIT1();          // KV(kt) landed (this thread)
        __syncthreads();     // all threads' KV(kt) visible; prev compute done
        if (kt + 2 < 32) {
            kv_issue(sb, b, h, kt + 2, (kt + 2) % 3, tid);
            CP_COMMIT();
        }
        const uint32_t bufb = sb + (uint32_t)((kt % 3) * KV_BUF) * 2;

        // ---- S = Q K^T (3-term), ldmatrix.x4 fetches K for 2 n8 blocks ----
        float s[8][4];
#pragma unroll
        for (int j = 0; j < 8; j++)
#pragma unroll
            for (int e = 0; e < 4; e++) s[j][e] = 0.0f;
#pragma unroll
        for (int t = 0; t < 4; t++) {
#pragma unroll
            for (int jp = 0; jp < 4; jp++) {
                uint32_t ka = bufb + (uint32_t)(
                    (8 * (2 * jp + (lane >> 4)) + (lane & 7)) * FPK
                    + t * 16 + ((lane >> 3) & 1) * 8) * 2;
                uint32_t h0, h1, h2, h3, L0, L1, L2, L3;
                LDSM_X4(h0, h1, h2, h3, ka);
                LDSM_X4(L0, L1, L2, L3, ka + KV_TILE * 2);
                MMA16816(s[2 * jp],     qh[t], h0, h1);
                MMA16816(s[2 * jp],     qh[t], L0, L1);
                MMA16816(s[2 * jp],     ql[t], h0, h1);
                MMA16816(s[2 * jp + 1], qh[t], h2, h3);
                MMA16816(s[2 * jp + 1], qh[t], L2, L3);
                MMA16816(s[2 * jp + 1], ql[t], h2, h3);
            }
        }

        // ---- online softmax in registers ----
        float mx0 = s[0][0], mx1 = s[0][2];
#pragma unroll
        for (int j = 0; j < 8; j++) {
            mx0 = fmaxf(mx0, fmaxf(s[j][0], s[j][1]));
            mx1 = fmaxf(mx1, fmaxf(s[j][2], s[j][3]));
        }
        mx0 = fmaxf(mx0, __shfl_xor_sync(0xffffffffu, mx0, 1));
        mx0 = fmaxf(mx0, __shfl_xor_sync(0xffffffffu, mx0, 2));
        mx1 = fmaxf(mx1, __shfl_xor_sync(0xffffffffu, mx1, 1));
        mx1 = fmaxf(mx1, __shfl_xor_sync(0xffffffffu, mx1, 2));
        float m0n = fmaxf(m0, mx0), m1n = fmaxf(m1, mx1);
        float a0 = __expf(m0 - m0n), a1 = __expf(m1 - m1n);
        float sum0 = 0.0f, sum1 = 0.0f;
#pragma unroll
        for (int j = 0; j < 8; j++) {
            s[j][0] = __expf(s[j][0] - m0n); sum0 += s[j][0];
            s[j][1] = __expf(s[j][1] - m0n); sum0 += s[j][1];
            s[j][2] = __expf(s[j][2] - m1n); sum1 += s[j][2];
            s[j][3] = __expf(s[j][3] - m1n); sum1 += s[j][3];
        }
        sum0 += __shfl_xor_sync(0xffffffffu, sum0, 1);
        sum0 += __shfl_xor_sync(0xffffffffu, sum0, 2);
        sum1 += __shfl_xor_sync(0xffffffffu, sum1, 1);
        sum1 += __shfl_xor_sync(0xffffffffu, sum1, 2);
        ls0 = ls0 * a0 + sum0; ls1 = ls1 * a1 + sum1;
        m0 = m0n; m1 = m1n;

        uint32_t pa[4][4];
#pragma unroll
        for (int t = 0; t < 4; t++) {
            pa[t][0] = pk2(s[2 * t][0],     s[2 * t][1]);
            pa[t][1] = pk2(s[2 * t][2],     s[2 * t][3]);
            pa[t][2] = pk2(s[2 * t + 1][0], s[2 * t + 1][1]);
            pa[t][3] = pk2(s[2 * t + 1][2], s[2 * t + 1][3]);
        }
#pragma unroll
        for (int j = 0; j < 8; j++) {
            o[j][0] *= a0; o[j][1] *= a0;
            o[j][2] *= a1; o[j][3] *= a1;
        }

        // ---- O += P V (2-term), x4 trans fetches V for 2 n8 blocks ----
#pragma unroll
        for (int t = 0; t < 4; t++) {
#pragma unroll
            for (int jp = 0; jp < 4; jp++) {
                uint32_t va = bufb + (uint32_t)(2 * KV_TILE
                                + (16 * t + l15) * FPK
                                + 8 * (2 * jp + (lane >> 4))) * 2;
                uint32_t v0, v1, v2, v3, u0, u1, u2, u3;
                LDSM_X4T(v0, v1, v2, v3, va);
                LDSM_X4T(u0, u1, u2, u3, va + KV_TILE * 2);
                MMA16816(o[2 * jp],     pa[t], v0, v1);
                MMA16816(o[2 * jp],     pa[t], u0, u1);
                MMA16816(o[2 * jp + 1], pa[t], v2, v3);
                MMA16816(o[2 * jp + 1], pa[t], u2, u3);
            }
        }
    }

    // ---- epilogue: normalize, split hi/lo, write g_ath/g_atl ----
    {
        float inv0 = 1.0f / ls0, inv1 = 1.0f / ls1;
        size_t row0 = (size_t)(b * NN + q0 + w * 16 + g);
        size_t row1 = row0 + 8;
        int col = h * 64 + 2 * tg;
#pragma unroll
        for (int j = 0; j < 8; j++) {
            size_t i0 = row0 * 1024 + col + 8 * j;
            size_t i1 = row1 * 1024 + col + 8 * j;
            float v00 = o[j][0] * inv0, v01 = o[j][1] * inv0;
            float v10 = o[j][2] * inv1, v11 = o[j][3] * inv1;
            __half h0, l0, h1, l1;
            split1(v00, h0, l0); split1(v01, h1, l1);
            *(__half2*)(g_ath + i0) = __halves2half2(h0, h1);
            *(__half2*)(g_atl + i0) = __halves2half2(l0, l1);
            split1(v10, h0, l0); split1(v11, h1, l1);
            *(__half2*)(g_ath + i1) = __halves2half2(h0, h1);
            *(__half2*)(g_atl + i1) = __halves2half2(l0, l1);
        }
    }
}

// ---------------------------------------------------------------------------
extern "C" void kernel_launch(void* const* d_in, const int* in_sizes, int n_in,
                              void* d_out, int out_size)
{
    const float* x      = (const float*)d_in[0];
    const float* w_qkv  = (const float*)d_in[1];
    const float* w_proj = (const float*)d_in[2];
    const float* b_proj = (const float*)d_in[3];
    float* out = (float*)d_out;

    void *xh, *xl, *wqh, *wql, *wph, *wpl, *qh, *ql, *ath, *atl;
    cudaGetSymbolAddress(&xh, g_xh);   cudaGetSymbolAddress(&xl, g_xl);
    cudaGetSymbolAddress(&wqh, g_wqh); cudaGetSymbolAddress(&wql, g_wql);
    cudaGetSymbolAddress(&wph, g_wph); cudaGetSymbolAddress(&wpl, g_wpl);
    cudaGetSymbolAddress(&qh, g_qkvh); cudaGetSymbolAddress(&ql, g_qkvl);
    cudaGetSymbolAddress(&ath, g_ath); cudaGetSymbolAddress(&atl, g_atl);

    cudaFuncSetAttribute(gemm_h, cudaFuncAttributeMaxDynamicSharedMemorySize, G_SMEM);
    cudaFuncSetAttribute(flash_r, cudaFuncAttributeMaxDynamicSharedMemorySize, F_SMEM);

    // split all inputs (one launch)
    splitall<<<8192, 256>>>(x, w_qkv, w_proj);

    // 1) qkv = x @ w_qkv -> g_qkvh/l (q columns pre-scaled by 1/8)
    gemm_h<<<dim3(24, 32), 256, G_SMEM>>>(
        (const __half*)xh, (const __half*)xl, (const __half*)wqh, (const __half*)wql,
        nullptr, nullptr, (__half*)qh, (__half*)ql, 4096, 3072, 1024, 0);
    // 2) flash attention -> g_ath/l
    flash_r<<<dim3(16, 32), 256, F_SMEM>>>();
    // 3) out = attn @ w_proj + b_proj
    gemm_h<<<dim3(8, 32), 256, G_SMEM>>>(
        (const __half*)ath, (const __half*)atl, (const __half*)wph, (const __half*)wpl,
        out, b_proj, nullptr, nullptr, 4096, 1024, 1024, 1);
}

// round 8
// speedup vs baseline: 1.0198x; 1.0198x over previous
#include <cuda_runtime.h>
#include <cuda_fp16.h>
#include <mma.h>
#include <cstdint>
#include <math.h>

using namespace nvcuda;

#define BB 2
#define NN 2048
#define CC 1024
#define HH 16
#define DD 64
#define INNER 1024
#define QK_SCALE 0.125f

// fp16 hi/lo split scratch
__device__ __half g_xh[4194304],  g_xl[4194304];
__device__ __half g_wqh[3145728], g_wql[3145728];
__device__ __half g_wph[1048576], g_wpl[1048576];
__device__ __half g_qkvh[12582912], g_qkvl[12582912];
__device__ __half g_ath[4194304], g_atl[4194304];

// ---------------------------------------------------------------------------
__device__ __forceinline__ uint32_t smem_u32(const void* p) {
    uint32_t a;
    asm("{ .reg .u64 t; cvta.to.shared.u64 t, %1; cvt.u32.u64 %0, t; }"
        : "=r"(a) : "l"(p));
    return a;
}
__device__ __forceinline__ void cp16(uint32_t dst, const void* src) {
    asm volatile("cp.async.cg.shared.global [%0], [%1], 16;"
                 :: "r"(dst), "l"(src));
}
#define CP_COMMIT() asm volatile("cp.async.commit_group;" ::: "memory")
#define CP_WAIT1()  asm volatile("cp.async.wait_group 1;" ::: "memory")
#define CP_WAIT0()  asm volatile("cp.async.wait_group 0;" ::: "memory")

#define LDSM_X4(r0,r1,r2,r3,addr) \
    asm volatile("ldmatrix.sync.aligned.m8n8.x4.shared.b16 {%0,%1,%2,%3}, [%4];" \
        : "=r"(r0),"=r"(r1),"=r"(r2),"=r"(r3) : "r"(addr))
#define LDSM_X4T(r0,r1,r2,r3,addr) \
    asm volatile("ldmatrix.sync.aligned.m8n8.x4.trans.shared.b16 {%0,%1,%2,%3}, [%4];" \
        : "=r"(r0),"=r"(r1),"=r"(r2),"=r"(r3) : "r"(addr))
#define MMA16816(c,a,b0,b1) \
    asm volatile("mma.sync.aligned.m16n8k16.row.col.f32.f16.f16.f32 " \
        "{%0,%1,%2,%3},{%4,%5,%6,%7},{%8,%9},{%0,%1,%2,%3};" \
        : "+f"((c)[0]),"+f"((c)[1]),"+f"((c)[2]),"+f"((c)[3]) \
        : "r"((a)[0]),"r"((a)[1]),"r"((a)[2]),"r"((a)[3]),"r"(b0),"r"(b1))

__device__ __forceinline__ uint32_t pk2(float lo, float hi) {
    uint32_t u;
    asm("cvt.rn.f16x2.f32 %0, %1, %2;" : "=r"(u) : "f"(hi), "f"(lo));
    return u;
}
__device__ __forceinline__ void split1(float v, __half& h, __half& l) {
    h = __float2half_rn(v);
    l = __float2half_rn(v - __half2float(h));
}

typedef wmma::fragment<wmma::matrix_a, 16, 16, 16, __half, wmma::row_major> HA;
typedef wmma::fragment<wmma::matrix_b, 16, 16, 16, __half, wmma::row_major> HBr;
typedef wmma::fragment<wmma::accumulator, 16, 16, 16, float> HC;

// ---------------------------------------------------------------------------
// Merged pre-split kernel
// ---------------------------------------------------------------------------
__global__ __launch_bounds__(256) void splitall(
    const float* __restrict__ x, const float* __restrict__ wq,
    const float* __restrict__ wp)
{
    int i = blockIdx.x * 256 + threadIdx.x;
    const float4* s;
    __half2 *hi, *lo;
    int j;
    if (i < 1048576) {
        s = (const float4*)x;  hi = (__half2*)g_xh;  lo = (__half2*)g_xl;  j = i;
    } else if (i < 1835008) {
        s = (const float4*)wq; hi = (__half2*)g_wqh; lo = (__half2*)g_wql; j = i - 1048576;
    } else {
        s = (const float4*)wp; hi = (__half2*)g_wph; lo = (__half2*)g_wpl; j = i - 1835008;
    }
    float4 v = s[j];
    __half h0, h1, h2, h3, l0, l1, l2, l3;
    split1(v.x, h0, l0); split1(v.y, h1, l1);
    split1(v.z, h2, l2); split1(v.w, h3, l3);
    hi[2 * j]     = __halves2half2(h0, h1);
    hi[2 * j + 1] = __halves2half2(h2, h3);
    lo[2 * j]     = __halves2half2(l0, l1);
    lo[2 * j + 1] = __halves2half2(l2, l3);
}

// ---------------------------------------------------------------------------
// fp16 split GEMM (wmma): 128x128 tile, 256 thr, K-step 32,
// 3-stage cp.async pipeline, one barrier per k-tile.
// ---------------------------------------------------------------------------
#define GP_A 40
#define GP_B 136
#define A_HALF (128 * GP_A)
#define B_HALF (32 * GP_B)
#define G_ABYTES (A_HALF * 2)
#define G_BBYTES (B_HALF * 2)
#define G_STAGE (2 * G_ABYTES + 2 * G_BBYTES)
#define G_SMEM (3 * G_STAGE)

__device__ __forceinline__ void g_issue(
    uint32_t sb, const __half* Ah, const __half* Al,
    const __half* Bh, const __half* Bl,
    int m0, int n0, int K, int N, int kt, int buf, int tid)
{
    uint32_t st = sb + (uint32_t)buf * G_STAGE;
#pragma unroll
    for (int i = 0; i < 4; i++) {
        int idx = tid + i * 256;
        int arr = idx >> 9, e = idx & 511;
        int r = e >> 2, f = e & 3;
        const __half* src = (arr ? Al : Ah) + (size_t)(m0 + r) * K + kt * 32 + f * 8;
        cp16(st + (uint32_t)arr * G_ABYTES + (uint32_t)(r * GP_A + f * 8) * 2, src);
    }
#pragma unroll
    for (int i = 0; i < 4; i++) {
        int idx = tid + i * 256;
        int arr = idx >> 9, e = idx & 511;
        int r = e >> 4, f = e & 15;
        const __half* src = (arr ? Bl : Bh) + (size_t)(kt * 32 + r) * N + n0 + f * 8;
        cp16(st + 2 * G_ABYTES + (uint32_t)arr * G_BBYTES
                + (uint32_t)(r * GP_B + f * 8) * 2, src);
    }
}

__global__ __launch_bounds__(256, 2) void gemm_h(
    const __half* __restrict__ Ah, const __half* __restrict__ Al,
    const __half* __restrict__ Bh, const __half* __restrict__ Bl,
    float* __restrict__ Cout, const float* __restrict__ bias,
    __half* __restrict__ Ch, __half* __restrict__ Cl,
    int M, int N, int K, int mode)
{
    extern __shared__ char sm[];
    const uint32_t sb = smem_u32(sm);
    const int tid = threadIdx.x;
    const int wid = tid >> 5;
    const int wm = wid & 3;
    const int wn = wid >> 2;
    const int m0 = blockIdx.y * 128;
    const int n0 = blockIdx.x * 128;

    HC acc[2][4];
#pragma unroll
    for (int i = 0; i < 2; i++)
#pragma unroll
        for (int j = 0; j < 4; j++) wmma::fill_fragment(acc[i][j], 0.0f);

    const int nkt = K / 32;
    g_issue(sb, Ah, Al, Bh, Bl, m0, n0, K, N, 0, 0, tid); CP_COMMIT();
    g_issue(sb, Ah, Al, Bh, Bl, m0, n0, K, N, 1, 1, tid); CP_COMMIT();

    for (int kt = 0; kt < nkt; kt++) {
        CP_WAIT1();
        __syncthreads();
        if (kt + 2 < nkt) {
            g_issue(sb, Ah, Al, Bh, Bl, m0, n0, K, N, kt + 2, (kt + 2) % 3, tid);
            CP_COMMIT();
        }
        const __half* st  = (const __half*)(sm + (size_t)(kt % 3) * G_STAGE);
        const __half* Ash = st;
        const __half* Asl = st + A_HALF;
        const __half* Bsh = st + 2 * A_HALF;
        const __half* Bsl = st + 2 * A_HALF + B_HALF;

#pragma unroll
        for (int s = 0; s < 2; s++) {
            HA ah[2], al[2];
#pragma unroll
            for (int i = 0; i < 2; i++) {
                wmma::load_matrix_sync(ah[i], Ash + (wm * 32 + i * 16) * GP_A + s * 16, GP_A);
                wmma::load_matrix_sync(al[i], Asl + (wm * 32 + i * 16) * GP_A + s * 16, GP_A);
            }
#pragma unroll
            for (int j = 0; j < 4; j++) {
                HBr bh, bl;
                wmma::load_matrix_sync(bh, Bsh + (s * 16) * GP_B + wn * 64 + j * 16, GP_B);
                wmma::load_matrix_sync(bl, Bsl + (s * 16) * GP_B + wn * 64 + j * 16, GP_B);
#pragma unroll
                for (int i = 0; i < 2; i++) {
                    wmma::mma_sync(acc[i][j], ah[i], bh, acc[i][j]);
                    wmma::mma_sync(acc[i][j], ah[i], bl, acc[i][j]);
                    wmma::mma_sync(acc[i][j], al[i], bh, acc[i][j]);
                }
            }
        }
    }
    CP_WAIT0();
    __syncthreads();

    float* Cs = (float*)sm;
#pragma unroll
    for (int i = 0; i < 2; i++)
#pragma unroll
        for (int j = 0; j < 4; j++)
            wmma::store_matrix_sync(Cs + (wm * 32 + i * 16) * 128 + wn * 64 + j * 16,
                                    acc[i][j], 128, wmma::mem_row_major);
    __syncthreads();
#pragma unroll
    for (int i = 0; i < 16; i++) {
        int idx = tid + i * 256;
        int r = idx >> 5, f = idx & 31;
        float4 v = *(float4*)(Cs + r * 128 + f * 4);
        int gc = n0 + f * 4;
        if (mode == 1) {
            const float* bp = bias + gc;
            v.x += bp[0]; v.y += bp[1]; v.z += bp[2]; v.w += bp[3];
            *(float4*)(Cout + (size_t)(m0 + r) * N + gc) = v;
        } else {
            float sc = (gc < 1024) ? QK_SCALE : 1.0f;
            v.x *= sc; v.y *= sc; v.z *= sc; v.w *= sc;
            __half h0, h1, h2, h3, l0, l1, l2, l3;
            split1(v.x, h0, l0); split1(v.y, h1, l1);
            split1(v.z, h2, l2); split1(v.w, h3, l3);
            __half2* ph = (__half2*)(Ch + (size_t)(m0 + r) * N + gc);
            __half2* pl = (__half2*)(Cl + (size_t)(m0 + r) * N + gc);
            ph[0] = __halves2half2(h0, h1); ph[1] = __halves2half2(h2, h3);
            pl[0] = __halves2half2(l0, l1); pl[1] = __halves2half2(l2, l3);
        }
    }
}

// ---------------------------------------------------------------------------
// Flash attention: double-buffered K/V + PERSISTENT Q smem region.
// qh in registers; ql re-fetched via ldmatrix each k-iteration.
// Pipeline ordering (race-free): wait(kt) -> barrier -> issue(kt+1) -> compute.
// ---------------------------------------------------------------------------
#define FPK 72                     // smem pitch in halves
#define KV_TILE 4608               // 64*72 halves per tile
#define KV_BUF 18432               // 4 tiles (Kh,Kl,Vh,Vl) in halves
#define Q_OFF (2 * KV_BUF)         // persistent Q region (halves offset)
#define F_SMEM (3 * KV_BUF * 2)    // 110592 bytes

__device__ __forceinline__ void kv_issue(uint32_t sb, int b, int h, int kt,
                                         int buf, int tid)
{
    size_t rowbase = (size_t)(b * NN + kt * 64) * 3072 + 1024 + h * 64;
#pragma unroll
    for (int i = 0; i < 8; i++) {
        int idx = tid + i * 256;
        int arr = idx >> 9;           // 0:Kh 1:Kl 2:Vh 3:Vl
        int e = idx & 511;
        int r = e >> 3, f = e & 7;
        const __half* src = ((arr & 1) ? g_qkvl : g_qkvh)
            + rowbase + (size_t)(arr >> 1) * 1024 + (size_t)r * 3072 + f * 8;
        uint32_t dst = sb + (uint32_t)(buf * KV_BUF + arr * KV_TILE + r * FPK + f * 8) * 2;
        cp16(dst, src);
    }
}

__global__ __launch_bounds__(256, 2) void flash_r()
{
    extern __shared__ char sm[];
    const uint32_t sb = smem_u32(sm);
    const int tid = threadIdx.x;
    const int w = tid >> 5;
    const int lane = tid & 31;
    const int l15 = lane & 15;
    const int g = lane >> 2;
    const int tg = lane & 3;
    const int b = blockIdx.y >> 4;
    const int h = blockIdx.y & 15;
    const int q0 = blockIdx.x * 128;

    // ---- prologue: Q (persistent region) + KV(0) in one group ----
    {
        size_t qrowbase = (size_t)(b * NN + q0) * 3072 + h * 64;
#pragma unroll
        for (int i = 0; i < 8; i++) {
            int idx = tid + i * 256;
            int arr = idx >> 10;          // 0: Qh, 1: Ql
            int e = idx & 1023;
            int r = e >> 3, f = e & 7;
            const __half* src = (arr ? g_qkvl : g_qkvh)
                + qrowbase + (size_t)r * 3072 + f * 8;
            uint32_t dst = sb + (uint32_t)(Q_OFF + arr * 9216 + r * FPK + f * 8) * 2;
            cp16(dst, src);
        }
    }
    kv_issue(sb, b, h, 0, 0, tid);
    CP_COMMIT();
    CP_WAIT0();
    __syncthreads();

    // qh persistent in registers; ql stays in smem (reloaded per k-iter)
    const uint32_t qaddr_base =
        sb + (uint32_t)(Q_OFF + (w * 16 + l15) * FPK + (lane >> 4) * 8) * 2;
    uint32_t qh[4][4];
#pragma unroll
    for (int t = 0; t < 4; t++)
        LDSM_X4(qh[t][0], qh[t][1], qh[t][2], qh[t][3], qaddr_base + (uint32_t)(t * 32));

    float o[8][4];
#pragma unroll
    for (int j = 0; j < 8; j++)
#pragma unroll
        for (int e = 0; e < 4; e++) o[j][e] = 0.0f;
    float m0 = -INFINITY, m1 = -INFINITY, ls0 = 0.0f, ls1 = 0.0f;

    for (int kt = 0; kt < 32; kt++) {
        CP_WAIT0();          // kv(kt) landed locally
        __syncthreads();     // visible to all; previous compute done
        if (kt + 1 < 32) {   // safe now: everyone is past compute(kt-1)
            kv_issue(sb, b, h, kt + 1, (kt + 1) & 1, tid);
            CP_COMMIT();
        }
        const uint32_t bufb = sb + (uint32_t)((kt & 1) * KV_BUF) * 2;

        // ---- S = Q K^T (3-term) ----
        float s[8][4];
#pragma unroll
        for (int j = 0; j < 8; j++)
#pragma unroll
            for (int e = 0; e < 4; e++) s[j][e] = 0.0f;
#pragma unroll
        for (int t = 0; t < 4; t++) {
            uint32_t ql_t[4];
            LDSM_X4(ql_t[0], ql_t[1], ql_t[2], ql_t[3],
                    qaddr_base + (uint32_t)(t * 32) + 9216 * 2);
#pragma unroll
            for (int jp = 0; jp < 4; jp++) {
                uint32_t ka = bufb + (uint32_t)(
                    (8 * (2 * jp + (lane >> 4)) + (lane & 7)) * FPK
                    + t * 16 + ((lane >> 3) & 1) * 8) * 2;
                uint32_t h0, h1, h2, h3, L0, L1, L2, L3;
                LDSM_X4(h0, h1, h2, h3, ka);
                LDSM_X4(L0, L1, L2, L3, ka + KV_TILE * 2);
                MMA16816(s[2 * jp],     qh[t], h0, h1);
                MMA16816(s[2 * jp],     qh[t], L0, L1);
                MMA16816(s[2 * jp],     ql_t,  h0, h1);
                MMA16816(s[2 * jp + 1], qh[t], h2, h3);
                MMA16816(s[2 * jp + 1], qh[t], L2, L3);
                MMA16816(s[2 * jp + 1], ql_t,  h2, h3);
            }
        }

        // ---- online softmax in registers ----
        float mx0 = s[0][0], mx1 = s[0][2];
#pragma unroll
        for (int j = 0; j < 8; j++) {
            mx0 = fmaxf(mx0, fmaxf(s[j][0], s[j][1]));
            mx1 = fmaxf(mx1, fmaxf(s[j][2], s[j][3]));
        }
        mx0 = fmaxf(mx0, __shfl_xor_sync(0xffffffffu, mx0, 1));
        mx0 = fmaxf(mx0, __shfl_xor_sync(0xffffffffu, mx0, 2));
        mx1 = fmaxf(mx1, __shfl_xor_sync(0xffffffffu, mx1, 1));
        mx1 = fmaxf(mx1, __shfl_xor_sync(0xffffffffu, mx1, 2));
        float m0n = fmaxf(m0, mx0), m1n = fmaxf(m1, mx1);
        float a0 = __expf(m0 - m0n), a1 = __expf(m1 - m1n);
        float sum0 = 0.0f, sum1 = 0.0f;
#pragma unroll
        for (int j = 0; j < 8; j++) {
            s[j][0] = __expf(s[j][0] - m0n); sum0 += s[j][0];
            s[j][1] = __expf(s[j][1] - m0n); sum0 += s[j][1];
            s[j][2] = __expf(s[j][2] - m1n); sum1 += s[j][2];
            s[j][3] = __expf(s[j][3] - m1n); sum1 += s[j][3];
        }
        sum0 += __shfl_xor_sync(0xffffffffu, sum0, 1);
        sum0 += __shfl_xor_sync(0xffffffffu, sum0, 2);
        sum1 += __shfl_xor_sync(0xffffffffu, sum1, 1);
        sum1 += __shfl_xor_sync(0xffffffffu, sum1, 2);
        ls0 = ls0 * a0 + sum0; ls1 = ls1 * a1 + sum1;
        m0 = m0n; m1 = m1n;

        uint32_t pa[4][4];
#pragma unroll
        for (int t = 0; t < 4; t++) {
            pa[t][0] = pk2(s[2 * t][0],     s[2 * t][1]);
            pa[t][1] = pk2(s[2 * t][2],     s[2 * t][3]);
            pa[t][2] = pk2(s[2 * t + 1][0], s[2 * t + 1][1]);
            pa[t][3] = pk2(s[2 * t + 1][2], s[2 * t + 1][3]);
        }
#pragma unroll
        for (int j = 0; j < 8; j++) {
            o[j][0] *= a0; o[j][1] *= a0;
            o[j][2] *= a1; o[j][3] *= a1;
        }

        // ---- O += P V (2-term) ----
#pragma unroll
        for (int t = 0; t < 4; t++) {
#pragma unroll
            for (int jp = 0; jp < 4; jp++) {
                uint32_t va = bufb + (uint32_t)(2 * KV_TILE
                                + (16 * t + l15) * FPK
                                + 8 * (2 * jp + (lane >> 4))) * 2;
                uint32_t v0, v1, v2, v3, u0, u1, u2, u3;
                LDSM_X4T(v0, v1, v2, v3, va);
                LDSM_X4T(u0, u1, u2, u3, va + KV_TILE * 2);
                MMA16816(o[2 * jp],     pa[t], v0, v1);
                MMA16816(o[2 * jp],     pa[t], u0, u1);
                MMA16816(o[2 * jp + 1], pa[t], v2, v3);
                MMA16816(o[2 * jp + 1], pa[t], u2, u3);
            }
        }
    }

    // ---- epilogue ----
    {
        float inv0 = 1.0f / ls0, inv1 = 1.0f / ls1;
        size_t row0 = (size_t)(b * NN + q0 + w * 16 + g);
        size_t row1 = row0 + 8;
        int col = h * 64 + 2 * tg;
#pragma unroll
        for (int j = 0; j < 8; j++) {
            size_t i0 = row0 * 1024 + col + 8 * j;
            size_t i1 = row1 * 1024 + col + 8 * j;
            float v00 = o[j][0] * inv0, v01 = o[j][1] * inv0;
            float v10 = o[j][2] * inv1, v11 = o[j][3] * inv1;
            __half h0, l0, h1, l1;
            split1(v00, h0, l0); split1(v01, h1, l1);
            *(__half2*)(g_ath + i0) = __halves2half2(h0, h1);
            *(__half2*)(g_atl + i0) = __halves2half2(l0, l1);
            split1(v10, h0, l0); split1(v11, h1, l1);
            *(__half2*)(g_ath + i1) = __halves2half2(h0, h1);
            *(__half2*)(g_atl + i1) = __halves2half2(l0, l1);
        }
    }
}

// ---------------------------------------------------------------------------
extern "C" void kernel_launch(void* const* d_in, const int* in_sizes, int n_in,
                              void* d_out, int out_size)
{
    const float* x      = (const float*)d_in[0];
    const float* w_qkv  = (const float*)d_in[1];
    const float* w_proj = (const float*)d_in[2];
    const float* b_proj = (const float*)d_in[3];
    float* out = (float*)d_out;

    void *xh, *xl, *wqh, *wql, *wph, *wpl, *qh, *ql, *ath, *atl;
    cudaGetSymbolAddress(&xh, g_xh);   cudaGetSymbolAddress(&xl, g_xl);
    cudaGetSymbolAddress(&wqh, g_wqh); cudaGetSymbolAddress(&wql, g_wql);
    cudaGetSymbolAddress(&wph, g_wph); cudaGetSymbolAddress(&wpl, g_wpl);
    cudaGetSymbolAddress(&qh, g_qkvh); cudaGetSymbolAddress(&ql, g_qkvl);
    cudaGetSymbolAddress(&ath, g_ath); cudaGetSymbolAddress(&atl, g_atl);

    cudaFuncSetAttribute(gemm_h, cudaFuncAttributeMaxDynamicSharedMemorySize, G_SMEM);
    cudaFuncSetAttribute(flash_r, cudaFuncAttributeMaxDynamicSharedMemorySize, F_SMEM);

    splitall<<<8192, 256>>>(x, w_qkv, w_proj);

    // 1) qkv = x @ w_qkv -> g_qkvh/l (q columns pre-scaled by 1/8)
    gemm_h<<<dim3(24, 32), 256, G_SMEM>>>(
        (const __half*)xh, (const __half*)xl, (const __half*)wqh, (const __half*)wql,
        nullptr, nullptr, (__half*)qh, (__half*)ql, 4096, 3072, 1024, 0);
    // 2) flash attention -> g_ath/l
    flash_r<<<dim3(16, 32), 256, F_SMEM>>>();
    // 3) out = attn @ w_proj + b_proj
    gemm_h<<<dim3(8, 32), 256, G_SMEM>>>(
        (const __half*)ath, (const __half*)atl, (const __half*)wph, (const __half*)wpl,
        out, b_proj, nullptr, nullptr, 4096, 1024, 1024, 1);
}

// round 9
// speedup vs baseline: 1.1587x; 1.1362x over previous
#include <cuda_runtime.h>
#include <cuda_fp16.h>
#include <mma.h>
#include <cstdint>
#include <math.h>

using namespace nvcuda;

#define BB 2
#define NN 2048
#define CC 1024
#define HH 16
#define DD 64
#define INNER 1024
#define QK_SCALE 0.125f

// fp16 hi/lo split scratch
__device__ __half g_xh[4194304],  g_xl[4194304];
__device__ __half g_wqh[3145728], g_wql[3145728];
__device__ __half g_wph[1048576], g_wpl[1048576];
__device__ __half g_qkvh[12582912], g_qkvl[12582912];
__device__ __half g_ath[4194304];          // attn out, hi only (gemm2 is 2-term)

// ---------------------------------------------------------------------------
__device__ __forceinline__ uint32_t smem_u32(const void* p) {
    uint32_t a;
    asm("{ .reg .u64 t; cvta.to.shared.u64 t, %1; cvt.u32.u64 %0, t; }"
        : "=r"(a) : "l"(p));
    return a;
}
__device__ __forceinline__ void cp16(uint32_t dst, const void* src) {
    asm volatile("cp.async.cg.shared.global [%0], [%1], 16;"
                 :: "r"(dst), "l"(src));
}
#define CP_COMMIT() asm volatile("cp.async.commit_group;" ::: "memory")
#define CP_WAIT1()  asm volatile("cp.async.wait_group 1;" ::: "memory")
#define CP_WAIT0()  asm volatile("cp.async.wait_group 0;" ::: "memory")

#define LDSM_X4(r0,r1,r2,r3,addr) \
    asm volatile("ldmatrix.sync.aligned.m8n8.x4.shared.b16 {%0,%1,%2,%3}, [%4];" \
        : "=r"(r0),"=r"(r1),"=r"(r2),"=r"(r3) : "r"(addr))
#define LDSM_X4T(r0,r1,r2,r3,addr) \
    asm volatile("ldmatrix.sync.aligned.m8n8.x4.trans.shared.b16 {%0,%1,%2,%3}, [%4];" \
        : "=r"(r0),"=r"(r1),"=r"(r2),"=r"(r3) : "r"(addr))
#define MMA16816(c,a,b0,b1) \
    asm volatile("mma.sync.aligned.m16n8k16.row.col.f32.f16.f16.f32 " \
        "{%0,%1,%2,%3},{%4,%5,%6,%7},{%8,%9},{%0,%1,%2,%3};" \
        : "+f"((c)[0]),"+f"((c)[1]),"+f"((c)[2]),"+f"((c)[3]) \
        : "r"((a)[0]),"r"((a)[1]),"r"((a)[2]),"r"((a)[3]),"r"(b0),"r"(b1))

__device__ __forceinline__ uint32_t pk2(float lo, float hi) {
    uint32_t u;
    asm("cvt.rn.f16x2.f32 %0, %1, %2;" : "=r"(u) : "f"(hi), "f"(lo));
    return u;
}
__device__ __forceinline__ void split1(float v, __half& h, __half& l) {
    h = __float2half_rn(v);
    l = __float2half_rn(v - __half2float(h));
}

typedef wmma::fragment<wmma::matrix_a, 16, 16, 16, __half, wmma::row_major> HA;
typedef wmma::fragment<wmma::matrix_b, 16, 16, 16, __half, wmma::row_major> HBr;
typedef wmma::fragment<wmma::accumulator, 16, 16, 16, float> HC;

// ---------------------------------------------------------------------------
// Merged pre-split kernel
// ---------------------------------------------------------------------------
__global__ __launch_bounds__(256) void splitall(
    const float* __restrict__ x, const float* __restrict__ wq,
    const float* __restrict__ wp)
{
    int i = blockIdx.x * 256 + threadIdx.x;
    const float4* s;
    __half2 *hi, *lo;
    int j;
    if (i < 1048576) {
        s = (const float4*)x;  hi = (__half2*)g_xh;  lo = (__half2*)g_xl;  j = i;
    } else if (i < 1835008) {
        s = (const float4*)wq; hi = (__half2*)g_wqh; lo = (__half2*)g_wql; j = i - 1048576;
    } else {
        s = (const float4*)wp; hi = (__half2*)g_wph; lo = (__half2*)g_wpl; j = i - 1835008;
    }
    float4 v = s[j];
    __half h0, h1, h2, h3, l0, l1, l2, l3;
    split1(v.x, h0, l0); split1(v.y, h1, l1);
    split1(v.z, h2, l2); split1(v.w, h3, l3);
    hi[2 * j]     = __halves2half2(h0, h1);
    hi[2 * j + 1] = __halves2half2(h2, h3);
    lo[2 * j]     = __halves2half2(l0, l1);
    lo[2 * j + 1] = __halves2half2(l2, l3);
}

// ---------------------------------------------------------------------------
// fp16 split GEMM (wmma): 128x128 tile, 256 thr, K-step 32, 3-stage cp.async.
// USE_AL=1: 3-term (Ah*Bh + Ah*Bl + Al*Bh).  USE_AL=0: 2-term (skip Al).
// ---------------------------------------------------------------------------
#define GP_A 40
#define GP_B 136
#define A_HALF (128 * GP_A)
#define B_HALF (32 * GP_B)
#define G_ABYTES (A_HALF * 2)
#define G_BBYTES (B_HALF * 2)
#define G_STAGE (2 * G_ABYTES + 2 * G_BBYTES)
#define G_SMEM (3 * G_STAGE)

__device__ __forceinline__ void g_issue(
    uint32_t sb, const __half* Ah, const __half* Al,
    const __half* Bh, const __half* Bl,
    int m0, int n0, int K, int N, int kt, int buf, int tid, int use_al)
{
    uint32_t st = sb + (uint32_t)buf * G_STAGE;
#pragma unroll
    for (int i = 0; i < 4; i++) {
        int idx = tid + i * 256;
        int arr = idx >> 9, e = idx & 511;
        int r = e >> 2, f = e & 3;
        if (arr == 0 || use_al) {
            const __half* src = (arr ? Al : Ah) + (size_t)(m0 + r) * K + kt * 32 + f * 8;
            cp16(st + (uint32_t)arr * G_ABYTES + (uint32_t)(r * GP_A + f * 8) * 2, src);
        }
    }
#pragma unroll
    for (int i = 0; i < 4; i++) {
        int idx = tid + i * 256;
        int arr = idx >> 9, e = idx & 511;
        int r = e >> 4, f = e & 15;
        const __half* src = (arr ? Bl : Bh) + (size_t)(kt * 32 + r) * N + n0 + f * 8;
        cp16(st + 2 * G_ABYTES + (uint32_t)arr * G_BBYTES
                + (uint32_t)(r * GP_B + f * 8) * 2, src);
    }
}

template <int USE_AL>
__global__ __launch_bounds__(256, 2) void gemm_h(
    const __half* __restrict__ Ah, const __half* __restrict__ Al,
    const __half* __restrict__ Bh, const __half* __restrict__ Bl,
    float* __restrict__ Cout, const float* __restrict__ bias,
    __half* __restrict__ Ch, __half* __restrict__ Cl,
    int M, int N, int K, int mode)
{
    extern __shared__ char sm[];
    const uint32_t sb = smem_u32(sm);
    const int tid = threadIdx.x;
    const int wid = tid >> 5;
    const int wm = wid & 3;
    const int wn = wid >> 2;
    const int m0 = blockIdx.y * 128;
    const int n0 = blockIdx.x * 128;

    HC acc[2][4];
#pragma unroll
    for (int i = 0; i < 2; i++)
#pragma unroll
        for (int j = 0; j < 4; j++) wmma::fill_fragment(acc[i][j], 0.0f);

    const int nkt = K / 32;
    g_issue(sb, Ah, Al, Bh, Bl, m0, n0, K, N, 0, 0, tid, USE_AL); CP_COMMIT();
    g_issue(sb, Ah, Al, Bh, Bl, m0, n0, K, N, 1, 1, tid, USE_AL); CP_COMMIT();

    for (int kt = 0; kt < nkt; kt++) {
        CP_WAIT1();
        __syncthreads();
        if (kt + 2 < nkt) {
            g_issue(sb, Ah, Al, Bh, Bl, m0, n0, K, N, kt + 2, (kt + 2) % 3, tid, USE_AL);
            CP_COMMIT();
        }
        const __half* st  = (const __half*)(sm + (size_t)(kt % 3) * G_STAGE);
        const __half* Ash = st;
        const __half* Asl = st + A_HALF;
        const __half* Bsh = st + 2 * A_HALF;
        const __half* Bsl = st + 2 * A_HALF + B_HALF;

#pragma unroll
        for (int s = 0; s < 2; s++) {
            HA ah[2], al[2];
#pragma unroll
            for (int i = 0; i < 2; i++) {
                wmma::load_matrix_sync(ah[i], Ash + (wm * 32 + i * 16) * GP_A + s * 16, GP_A);
                if (USE_AL)
                    wmma::load_matrix_sync(al[i], Asl + (wm * 32 + i * 16) * GP_A + s * 16, GP_A);
            }
#pragma unroll
            for (int j = 0; j < 4; j++) {
                HBr bh, bl;
                wmma::load_matrix_sync(bh, Bsh + (s * 16) * GP_B + wn * 64 + j * 16, GP_B);
                wmma::load_matrix_sync(bl, Bsl + (s * 16) * GP_B + wn * 64 + j * 16, GP_B);
#pragma unroll
                for (int i = 0; i < 2; i++) {
                    wmma::mma_sync(acc[i][j], ah[i], bh, acc[i][j]);
                    wmma::mma_sync(acc[i][j], ah[i], bl, acc[i][j]);
                    if (USE_AL)
                        wmma::mma_sync(acc[i][j], al[i], bh, acc[i][j]);
                }
            }
        }
    }
    CP_WAIT0();
    __syncthreads();

    float* Cs = (float*)sm;
#pragma unroll
    for (int i = 0; i < 2; i++)
#pragma unroll
        for (int j = 0; j < 4; j++)
            wmma::store_matrix_sync(Cs + (wm * 32 + i * 16) * 128 + wn * 64 + j * 16,
                                    acc[i][j], 128, wmma::mem_row_major);
    __syncthreads();
#pragma unroll
    for (int i = 0; i < 16; i++) {
        int idx = tid + i * 256;
        int r = idx >> 5, f = idx & 31;
        float4 v = *(float4*)(Cs + r * 128 + f * 4);
        int gc = n0 + f * 4;
        if (mode == 1) {
            const float* bp = bias + gc;
            v.x += bp[0]; v.y += bp[1]; v.z += bp[2]; v.w += bp[3];
            *(float4*)(Cout + (size_t)(m0 + r) * N + gc) = v;
        } else {
            float sc = (gc < 1024) ? QK_SCALE : 1.0f;
            v.x *= sc; v.y *= sc; v.z *= sc; v.w *= sc;
            __half h0, h1, h2, h3, l0, l1, l2, l3;
            split1(v.x, h0, l0); split1(v.y, h1, l1);
            split1(v.z, h2, l2); split1(v.w, h3, l3);
            __half2* ph = (__half2*)(Ch + (size_t)(m0 + r) * N + gc);
            __half2* pl = (__half2*)(Cl + (size_t)(m0 + r) * N + gc);
            ph[0] = __halves2half2(h0, h1); ph[1] = __halves2half2(h2, h3);
            pl[0] = __halves2half2(l0, l1); pl[1] = __halves2half2(l2, l3);
        }
    }
}

// ---------------------------------------------------------------------------
// Flash attention: double-buffered K/V (Kh,Kl,Vh — V hi only) + persistent Q.
// QK 3-term, PV 1-term.  wait -> barrier -> issue(kt+1) -> compute.
// ---------------------------------------------------------------------------
#define FPK 72                     // smem pitch in halves
#define KV_TILE 4608               // 64*72 halves per tile
#define KV_BUF (3 * KV_TILE)       // 3 tiles (Kh,Kl,Vh) = 13824 halves
#define Q_OFF (2 * KV_BUF)         // 27648 halves
#define F_SMEM ((2 * KV_BUF + 2 * 9216) * 2)   // 92160 bytes

__device__ __forceinline__ void kv_issue(uint32_t sb, int b, int h, int kt,
                                         int buf, int tid)
{
    size_t rowbase = (size_t)(b * NN + kt * 64) * 3072 + 1024 + h * 64;
#pragma unroll
    for (int i = 0; i < 6; i++) {
        int idx = tid + i * 256;
        int arr = idx >> 9;           // 0:Kh 1:Kl 2:Vh
        int e = idx & 511;
        int r = e >> 3, f = e & 7;
        const __half* src = ((arr == 1) ? g_qkvl : g_qkvh)
            + rowbase + (size_t)(arr >> 1) * 1024 + (size_t)r * 3072 + f * 8;
        uint32_t dst = sb + (uint32_t)(buf * KV_BUF + arr * KV_TILE + r * FPK + f * 8) * 2;
        cp16(dst, src);
    }
}

__global__ __launch_bounds__(256, 2) void flash_r()
{
    extern __shared__ char sm[];
    const uint32_t sb = smem_u32(sm);
    const int tid = threadIdx.x;
    const int w = tid >> 5;
    const int lane = tid & 31;
    const int l15 = lane & 15;
    const int g = lane >> 2;
    const int tg = lane & 3;
    const int b = blockIdx.y >> 4;
    const int h = blockIdx.y & 15;
    const int q0 = blockIdx.x * 128;

    // ---- prologue: Q (persistent) + KV(0) ----
    {
        size_t qrowbase = (size_t)(b * NN + q0) * 3072 + h * 64;
#pragma unroll
        for (int i = 0; i < 8; i++) {
            int idx = tid + i * 256;
            int arr = idx >> 10;          // 0: Qh, 1: Ql
            int e = idx & 1023;
            int r = e >> 3, f = e & 7;
            const __half* src = (arr ? g_qkvl : g_qkvh)
                + qrowbase + (size_t)r * 3072 + f * 8;
            uint32_t dst = sb + (uint32_t)(Q_OFF + arr * 9216 + r * FPK + f * 8) * 2;
            cp16(dst, src);
        }
    }
    kv_issue(sb, b, h, 0, 0, tid);
    CP_COMMIT();
    CP_WAIT0();
    __syncthreads();

    const uint32_t qaddr_base =
        sb + (uint32_t)(Q_OFF + (w * 16 + l15) * FPK + (lane >> 4) * 8) * 2;
    uint32_t qh[4][4];
#pragma unroll
    for (int t = 0; t < 4; t++)
        LDSM_X4(qh[t][0], qh[t][1], qh[t][2], qh[t][3], qaddr_base + (uint32_t)(t * 32));

    float o[8][4];
#pragma unroll
    for (int j = 0; j < 8; j++)
#pragma unroll
        for (int e = 0; e < 4; e++) o[j][e] = 0.0f;
    float m0 = -INFINITY, m1 = -INFINITY, ls0 = 0.0f, ls1 = 0.0f;

    for (int kt = 0; kt < 32; kt++) {
        CP_WAIT0();          // kv(kt) landed locally
        __syncthreads();     // visible to all; previous compute done
        if (kt + 1 < 32) {   // safe: everyone past compute(kt-1)
            kv_issue(sb, b, h, kt + 1, (kt + 1) & 1, tid);
            CP_COMMIT();
        }
        const uint32_t bufb = sb + (uint32_t)((kt & 1) * KV_BUF) * 2;

        // ---- S = Q K^T (3-term) ----
        float s[8][4];
#pragma unroll
        for (int j = 0; j < 8; j++)
#pragma unroll
            for (int e = 0; e < 4; e++) s[j][e] = 0.0f;
#pragma unroll
        for (int t = 0; t < 4; t++) {
            uint32_t ql_t[4];
            LDSM_X4(ql_t[0], ql_t[1], ql_t[2], ql_t[3],
                    qaddr_base + (uint32_t)(t * 32) + 9216 * 2);
#pragma unroll
            for (int jp = 0; jp < 4; jp++) {
                uint32_t ka = bufb + (uint32_t)(
                    (8 * (2 * jp + (lane >> 4)) + (lane & 7)) * FPK
                    + t * 16 + ((lane >> 3) & 1) * 8) * 2;
                uint32_t h0, h1, h2, h3, L0, L1, L2, L3;
                LDSM_X4(h0, h1, h2, h3, ka);
                LDSM_X4(L0, L1, L2, L3, ka + KV_TILE * 2);
                MMA16816(s[2 * jp],     qh[t], h0, h1);
                MMA16816(s[2 * jp],     qh[t], L0, L1);
                MMA16816(s[2 * jp],     ql_t,  h0, h1);
                MMA16816(s[2 * jp + 1], qh[t], h2, h3);
                MMA16816(s[2 * jp + 1], qh[t], L2, L3);
                MMA16816(s[2 * jp + 1], ql_t,  h2, h3);
            }
        }

        // ---- online softmax in registers ----
        float mx0 = s[0][0], mx1 = s[0][2];
#pragma unroll
        for (int j = 0; j < 8; j++) {
            mx0 = fmaxf(mx0, fmaxf(s[j][0], s[j][1]));
            mx1 = fmaxf(mx1, fmaxf(s[j][2], s[j][3]));
        }
        mx0 = fmaxf(mx0, __shfl_xor_sync(0xffffffffu, mx0, 1));
        mx0 = fmaxf(mx0, __shfl_xor_sync(0xffffffffu, mx0, 2));
        mx1 = fmaxf(mx1, __shfl_xor_sync(0xffffffffu, mx1, 1));
        mx1 = fmaxf(mx1, __shfl_xor_sync(0xffffffffu, mx1, 2));
        float m0n = fmaxf(m0, mx0), m1n = fmaxf(m1, mx1);
        float a0 = __expf(m0 - m0n), a1 = __expf(m1 - m1n);
        float sum0 = 0.0f, sum1 = 0.0f;
#pragma unroll
        for (int j = 0; j < 8; j++) {
            s[j][0] = __expf(s[j][0] - m0n); sum0 += s[j][0];
            s[j][1] = __expf(s[j][1] - m0n); sum0 += s[j][1];
            s[j][2] = __expf(s[j][2] - m1n); sum1 += s[j][2];
            s[j][3] = __expf(s[j][3] - m1n); sum1 += s[j][3];
        }
        sum0 += __shfl_xor_sync(0xffffffffu, sum0, 1);
        sum0 += __shfl_xor_sync(0xffffffffu, sum0, 2);
        sum1 += __shfl_xor_sync(0xffffffffu, sum1, 1);
        sum1 += __shfl_xor_sync(0xffffffffu, sum1, 2);
        ls0 = ls0 * a0 + sum0; ls1 = ls1 * a1 + sum1;
        m0 = m0n; m1 = m1n;

        uint32_t pa[4][4];
#pragma unroll
        for (int t = 0; t < 4; t++) {
            pa[t][0] = pk2(s[2 * t][0],     s[2 * t][1]);
            pa[t][1] = pk2(s[2 * t][2],     s[2 * t][3]);
            pa[t][2] = pk2(s[2 * t + 1][0], s[2 * t + 1][1]);
            pa[t][3] = pk2(s[2 * t + 1][2], s[2 * t + 1][3]);
        }
#pragma unroll
        for (int j = 0; j < 8; j++) {
            o[j][0] *= a0; o[j][1] *= a0;
            o[j][2] *= a1; o[j][3] *= a1;
        }

        // ---- O += P V (1-term: V hi only) ----
#pragma unroll
        for (int t = 0; t < 4; t++) {
#pragma unroll
            for (int jp = 0; jp < 4; jp++) {
                uint32_t va = bufb + (uint32_t)(2 * KV_TILE
                                + (16 * t + l15) * FPK
                                + 8 * (2 * jp + (lane >> 4))) * 2;
                uint32_t v0, v1, v2, v3;
                LDSM_X4T(v0, v1, v2, v3, va);
                MMA16816(o[2 * jp],     pa[t], v0, v1);
                MMA16816(o[2 * jp + 1], pa[t], v2, v3);
            }
        }
    }

    // ---- epilogue: normalize, write fp16 hi only (gemm2 is 2-term) ----
    {
        float inv0 = 1.0f / ls0, inv1 = 1.0f / ls1;
        size_t row0 = (size_t)(b * NN + q0 + w * 16 + g);
        size_t row1 = row0 + 8;
        int col = h * 64 + 2 * tg;
#pragma unroll
        for (int j = 0; j < 8; j++) {
            size_t i0 = row0 * 1024 + col + 8 * j;
            size_t i1 = row1 * 1024 + col + 8 * j;
            *(__half2*)(g_ath + i0) = __halves2half2(
                __float2half_rn(o[j][0] * inv0), __float2half_rn(o[j][1] * inv0));
            *(__half2*)(g_ath + i1) = __halves2half2(
                __float2half_rn(o[j][2] * inv1), __float2half_rn(o[j][3] * inv1));
        }
    }
}

// ---------------------------------------------------------------------------
extern "C" void kernel_launch(void* const* d_in, const int* in_sizes, int n_in,
                              void* d_out, int out_size)
{
    const float* x      = (const float*)d_in[0];
    const float* w_qkv  = (const float*)d_in[1];
    const float* w_proj = (const float*)d_in[2];
    const float* b_proj = (const float*)d_in[3];
    float* out = (float*)d_out;

    void *xh, *xl, *wqh, *wql, *wph, *wpl, *qh, *ql, *ath;
    cudaGetSymbolAddress(&xh, g_xh);   cudaGetSymbolAddress(&xl, g_xl);
    cudaGetSymbolAddress(&wqh, g_wqh); cudaGetSymbolAddress(&wql, g_wql);
    cudaGetSymbolAddress(&wph, g_wph); cudaGetSymbolAddress(&wpl, g_wpl);
    cudaGetSymbolAddress(&qh, g_qkvh); cudaGetSymbolAddress(&ql, g_qkvl);
    cudaGetSymbolAddress(&ath, g_ath);

    cudaFuncSetAttribute(gemm_h<1>, cudaFuncAttributeMaxDynamicSharedMemorySize, G_SMEM);
    cudaFuncSetAttribute(gemm_h<0>, cudaFuncAttributeMaxDynamicSharedMemorySize, G_SMEM);
    cudaFuncSetAttribute(flash_r, cudaFuncAttributeMaxDynamicSharedMemorySize, F_SMEM);

    splitall<<<8192, 256>>>(x, w_qkv, w_proj);

    // 1) qkv = x @ w_qkv -> g_qkvh/l (3-term; q columns pre-scaled by 1/8)
    gemm_h<1><<<dim3(24, 32), 256, G_SMEM>>>(
        (const __half*)xh, (const __half*)xl, (const __half*)wqh, (const __half*)wql,
        nullptr, nullptr, (__half*)qh, (__half*)ql, 4096, 3072, 1024, 0);
    // 2) flash attention -> g_ath (hi only)
    flash_r<<<dim3(16, 32), 256, F_SMEM>>>();
    // 3) out = attn @ w_proj + b_proj (2-term: Ah*Bh + Ah*Bl)
    gemm_h<0><<<dim3(8, 32), 256, G_SMEM>>>(
        (const __half*)ath, (const __half*)ath, (const __half*)wph, (const __half*)wpl,
        out, b_proj, nullptr, nullptr, 4096, 1024, 1024, 1);
}

// round 11
// speedup vs baseline: 1.5115x; 1.3045x over previous
#include <cuda_runtime.h>
#include <cuda_fp16.h>
#include <mma.h>
#include <cstdint>
#include <math.h>

using namespace nvcuda;

#define BB 2
#define NN 2048
#define CC 1024
#define HH 16
#define DD 64
#define INNER 1024
#define QK_SCALE 0.125f

// fp16 hi/lo split scratch
__device__ __half g_xh[4194304];                      // x hi only (gemm1 2-term)
__device__ __half g_wqh[3145728], g_wql[3145728];
__device__ __half g_wph[1048576], g_wpl[1048576];
__device__ __half g_qkvh[12582912];                   // q,k,v hi
__device__ __half g_qkvl[4194304];                    // q lo only (cols 0-1023)
__device__ __half g_ath[4194304];                     // attn out, hi only

// ---------------------------------------------------------------------------
__device__ __forceinline__ uint32_t smem_u32(const void* p) {
    uint32_t a;
    asm("{ .reg .u64 t; cvta.to.shared.u64 t, %1; cvt.u32.u64 %0, t; }"
        : "=r"(a) : "l"(p));
    return a;
}
__device__ __forceinline__ void cp16(uint32_t dst, const void* src) {
    asm volatile("cp.async.cg.shared.global [%0], [%1], 16;"
                 :: "r"(dst), "l"(src));
}
#define CP_COMMIT() asm volatile("cp.async.commit_group;" ::: "memory")
#define CP_WAIT1()  asm volatile("cp.async.wait_group 1;" ::: "memory")
#define CP_WAIT0()  asm volatile("cp.async.wait_group 0;" ::: "memory")

#define LDSM_X4(r0,r1,r2,r3,addr) \
    asm volatile("ldmatrix.sync.aligned.m8n8.x4.shared.b16 {%0,%1,%2,%3}, [%4];" \
        : "=r"(r0),"=r"(r1),"=r"(r2),"=r"(r3) : "r"(addr))
#define LDSM_X4T(r0,r1,r2,r3,addr) \
    asm volatile("ldmatrix.sync.aligned.m8n8.x4.trans.shared.b16 {%0,%1,%2,%3}, [%4];" \
        : "=r"(r0),"=r"(r1),"=r"(r2),"=r"(r3) : "r"(addr))
#define MMA16816(c,a,b0,b1) \
    asm volatile("mma.sync.aligned.m16n8k16.row.col.f32.f16.f16.f32 " \
        "{%0,%1,%2,%3},{%4,%5,%6,%7},{%8,%9},{%0,%1,%2,%3};" \
        : "+f"((c)[0]),"+f"((c)[1]),"+f"((c)[2]),"+f"((c)[3]) \
        : "r"((a)[0]),"r"((a)[1]),"r"((a)[2]),"r"((a)[3]),"r"(b0),"r"(b1))

__device__ __forceinline__ uint32_t pk2(float lo, float hi) {
    uint32_t u;
    asm("cvt.rn.f16x2.f32 %0, %1, %2;" : "=r"(u) : "f"(hi), "f"(lo));
    return u;
}
__device__ __forceinline__ void split1(float v, __half& h, __half& l) {
    h = __float2half_rn(v);
    l = __float2half_rn(v - __half2float(h));
}

typedef wmma::fragment<wmma::matrix_a, 16, 16, 16, __half, wmma::row_major> HA;
typedef wmma::fragment<wmma::matrix_b, 16, 16, 16, __half, wmma::row_major> HBr;
typedef wmma::fragment<wmma::accumulator, 16, 16, 16, float> HC;

// ---------------------------------------------------------------------------
// Pre-split: x -> hi only; w_qkv, w_proj -> hi+lo.
// ---------------------------------------------------------------------------
__global__ __launch_bounds__(256) void splitall(
    const float* __restrict__ x, const float* __restrict__ wq,
    const float* __restrict__ wp)
{
    int i = blockIdx.x * 256 + threadIdx.x;
    if (i < 1048576) {
        float4 v = ((const float4*)x)[i];
        __half2* hi = (__half2*)g_xh;
        hi[2 * i]     = __halves2half2(__float2half_rn(v.x), __float2half_rn(v.y));
        hi[2 * i + 1] = __halves2half2(__float2half_rn(v.z), __float2half_rn(v.w));
        return;
    }
    const float4* s;
    __half2 *hi, *lo;
    int j;
    if (i < 1835008) {
        s = (const float4*)wq; hi = (__half2*)g_wqh; lo = (__half2*)g_wql; j = i - 1048576;
    } else {
        s = (const float4*)wp; hi = (__half2*)g_wph; lo = (__half2*)g_wpl; j = i - 1835008;
    }
    float4 v = s[j];
    __half h0, h1, h2, h3, l0, l1, l2, l3;
    split1(v.x, h0, l0); split1(v.y, h1, l1);
    split1(v.z, h2, l2); split1(v.w, h3, l3);
    hi[2 * j]     = __halves2half2(h0, h1);
    hi[2 * j + 1] = __halves2half2(h2, h3);
    lo[2 * j]     = __halves2half2(l0, l1);
    lo[2 * j + 1] = __halves2half2(l2, l3);
}

// ---------------------------------------------------------------------------
// fp16 split GEMM (wmma): 128x128 tile, 256 thr, K-step 32, 3-stage cp.async.
// USE_AL=1: 3-term.  USE_AL=0: 2-term (Ah*Bh + Ah*Bl).
// mode 0 epilogue: hi for all cols; lo only for q cols (gc < 1024).
// ---------------------------------------------------------------------------
#define GP_A 40
#define GP_B 136
#define A_HALF (128 * GP_A)
#define B_HALF (32 * GP_B)
#define G_ABYTES (A_HALF * 2)
#define G_BBYTES (B_HALF * 2)
#define G_STAGE (2 * G_ABYTES + 2 * G_BBYTES)
#define G_SMEM (3 * G_STAGE)

__device__ __forceinline__ void g_issue(
    uint32_t sb, const __half* Ah, const __half* Al,
    const __half* Bh, const __half* Bl,
    int m0, int n0, int K, int N, int kt, int buf, int tid, int use_al)
{
    uint32_t st = sb + (uint32_t)buf * G_STAGE;
#pragma unroll
    for (int i = 0; i < 4; i++) {
        int idx = tid + i * 256;
        int arr = idx >> 9, e = idx & 511;
        int r = e >> 2, f = e & 3;
        if (arr == 0 || use_al) {
            const __half* src = (arr ? Al : Ah) + (size_t)(m0 + r) * K + kt * 32 + f * 8;
            cp16(st + (uint32_t)arr * G_ABYTES + (uint32_t)(r * GP_A + f * 8) * 2, src);
        }
    }
#pragma unroll
    for (int i = 0; i < 4; i++) {
        int idx = tid + i * 256;
        int arr = idx >> 9, e = idx & 511;
        int r = e >> 4, f = e & 15;
        const __half* src = (arr ? Bl : Bh) + (size_t)(kt * 32 + r) * N + n0 + f * 8;
        cp16(st + 2 * G_ABYTES + (uint32_t)arr * G_BBYTES
                + (uint32_t)(r * GP_B + f * 8) * 2, src);
    }
}

template <int USE_AL>
__global__ __launch_bounds__(256, 2) void gemm_h(
    const __half* __restrict__ Ah, const __half* __restrict__ Al,
    const __half* __restrict__ Bh, const __half* __restrict__ Bl,
    float* __restrict__ Cout, const float* __restrict__ bias,
    __half* __restrict__ Ch, __half* __restrict__ Cl,
    int M, int N, int K, int mode)
{
    extern __shared__ char sm[];
    const uint32_t sb = smem_u32(sm);
    const int tid = threadIdx.x;
    const int wid = tid >> 5;
    const int wm = wid & 3;
    const int wn = wid >> 2;
    const int m0 = blockIdx.y * 128;
    const int n0 = blockIdx.x * 128;

    HC acc[2][4];
#pragma unroll
    for (int i = 0; i < 2; i++)
#pragma unroll
        for (int j = 0; j < 4; j++) wmma::fill_fragment(acc[i][j], 0.0f);

    const int nkt = K / 32;
    g_issue(sb, Ah, Al, Bh, Bl, m0, n0, K, N, 0, 0, tid, USE_AL); CP_COMMIT();
    g_issue(sb, Ah, Al, Bh, Bl, m0, n0, K, N, 1, 1, tid, USE_AL); CP_COMMIT();

    for (int kt = 0; kt < nkt; kt++) {
        CP_WAIT1();
        __syncthreads();
        if (kt + 2 < nkt) {
            g_issue(sb, Ah, Al, Bh, Bl, m0, n0, K, N, kt + 2, (kt + 2) % 3, tid, USE_AL);
            CP_COMMIT();
        }
        const __half* st  = (const __half*)(sm + (size_t)(kt % 3) * G_STAGE);
        const __half* Ash = st;
        const __half* Asl = st + A_HALF;
        const __half* Bsh = st + 2 * A_HALF;
        const __half* Bsl = st + 2 * A_HALF + B_HALF;

#pragma unroll
        for (int s = 0; s < 2; s++) {
            HA ah[2], al[2];
#pragma unroll
            for (int i = 0; i < 2; i++) {
                wmma::load_matrix_sync(ah[i], Ash + (wm * 32 + i * 16) * GP_A + s * 16, GP_A);
                if (USE_AL)
                    wmma::load_matrix_sync(al[i], Asl + (wm * 32 + i * 16) * GP_A + s * 16, GP_A);
            }
#pragma unroll
            for (int j = 0; j < 4; j++) {
                HBr bh, bl;
                wmma::load_matrix_sync(bh, Bsh + (s * 16) * GP_B + wn * 64 + j * 16, GP_B);
                wmma::load_matrix_sync(bl, Bsl + (s * 16) * GP_B + wn * 64 + j * 16, GP_B);
#pragma unroll
                for (int i = 0; i < 2; i++) {
                    wmma::mma_sync(acc[i][j], ah[i], bh, acc[i][j]);
                    wmma::mma_sync(acc[i][j], ah[i], bl, acc[i][j]);
                    if (USE_AL)
                        wmma::mma_sync(acc[i][j], al[i], bh, acc[i][j]);
                }
            }
        }
    }
    CP_WAIT0();
    __syncthreads();

    float* Cs = (float*)sm;
#pragma unroll
    for (int i = 0; i < 2; i++)
#pragma unroll
        for (int j = 0; j < 4; j++)
            wmma::store_matrix_sync(Cs + (wm * 32 + i * 16) * 128 + wn * 64 + j * 16,
                                    acc[i][j], 128, wmma::mem_row_major);
    __syncthreads();
#pragma unroll
    for (int i = 0; i < 16; i++) {
        int idx = tid + i * 256;
        int r = idx >> 5, f = idx & 31;
        float4 v = *(float4*)(Cs + r * 128 + f * 4);
        int gc = n0 + f * 4;
        if (mode == 1) {
            const float* bp = bias + gc;
            v.x += bp[0]; v.y += bp[1]; v.z += bp[2]; v.w += bp[3];
            *(float4*)(Cout + (size_t)(m0 + r) * N + gc) = v;
        } else {
            if (gc < 1024) {
                // q columns: pre-scale by 1/8, write hi+lo (flash QK uses Ql)
                v.x *= QK_SCALE; v.y *= QK_SCALE; v.z *= QK_SCALE; v.w *= QK_SCALE;
                __half h0, h1, h2, h3, l0, l1, l2, l3;
                split1(v.x, h0, l0); split1(v.y, h1, l1);
                split1(v.z, h2, l2); split1(v.w, h3, l3);
                __half2* ph = (__half2*)(Ch + (size_t)(m0 + r) * N + gc);
                __half2* pl = (__half2*)(Cl + (size_t)(m0 + r) * 1024 + gc);
                ph[0] = __halves2half2(h0, h1); ph[1] = __halves2half2(h2, h3);
                pl[0] = __halves2half2(l0, l1); pl[1] = __halves2half2(l2, l3);
            } else {
                // k/v columns: hi only
                __half2* ph = (__half2*)(Ch + (size_t)(m0 + r) * N + gc);
                ph[0] = __halves2half2(__float2half_rn(v.x), __float2half_rn(v.y));
                ph[1] = __halves2half2(__float2half_rn(v.z), __float2half_rn(v.w));
            }
        }
    }
}

// ---------------------------------------------------------------------------
// Flash attention: double-buffered K/V (Kh, Vh only) + persistent Q (hi+lo).
// QK 2-term ((Qh+Ql)*Kh), PV 1-term. wait -> barrier -> issue(kt+1) -> compute.
// Q region: 128 rows x FPK pitch = 9216 halves PER ARRAY (hi, lo).
// ---------------------------------------------------------------------------
#define FPK 72                     // smem pitch in halves
#define KV_TILE 4608               // 64*72 halves per KV tile
#define KV_BUF (2 * KV_TILE)       // Kh + Vh = 9216 halves per buffer
#define Q_TILE 9216                // 128*72 halves per Q array
#define Q_OFF (2 * KV_BUF)         // 18432 halves
#define F_SMEM ((2 * KV_BUF + 2 * Q_TILE) * 2)   // 73728 bytes

__device__ __forceinline__ void kv_issue(uint32_t sb, int b, int h, int kt,
                                         int buf, int tid)
{
    size_t rowbase = (size_t)(b * NN + kt * 64) * 3072 + 1024 + h * 64;
#pragma unroll
    for (int i = 0; i < 4; i++) {
        int idx = tid + i * 256;
        int arr = idx >> 9;           // 0:Kh 1:Vh
        int e = idx & 511;
        int r = e >> 3, f = e & 7;
        const __half* src = g_qkvh + rowbase + (size_t)arr * 1024
                            + (size_t)r * 3072 + f * 8;
        uint32_t dst = sb + (uint32_t)(buf * KV_BUF + arr * KV_TILE + r * FPK + f * 8) * 2;
        cp16(dst, src);
    }
}

__global__ __launch_bounds__(256, 2) void flash_r()
{
    extern __shared__ char sm[];
    const uint32_t sb = smem_u32(sm);
    const int tid = threadIdx.x;
    const int w = tid >> 5;
    const int lane = tid & 31;
    const int l15 = lane & 15;
    const int g = lane >> 2;
    const int tg = lane & 3;
    const int b = blockIdx.y >> 4;
    const int h = blockIdx.y & 15;
    const int q0 = blockIdx.x * 128;

    // ---- prologue: Q hi (g_qkvh) + Q lo (g_qkvl) + KV(0) ----
    {
        size_t qrow_h = (size_t)(b * NN + q0) * 3072 + h * 64;
        size_t qrow_l = (size_t)(b * NN + q0) * 1024 + h * 64;
#pragma unroll
        for (int i = 0; i < 8; i++) {
            int idx = tid + i * 256;
            int arr = idx >> 10;          // 0: Qh, 1: Ql  (128 rows x 8 chunks each)
            int e = idx & 1023;
            int r = e >> 3, f = e & 7;
            const __half* src = arr
                ? g_qkvl + qrow_l + (size_t)r * 1024 + f * 8
                : g_qkvh + qrow_h + (size_t)r * 3072 + f * 8;
            uint32_t dst = sb + (uint32_t)(Q_OFF + arr * Q_TILE + r * FPK + f * 8) * 2;
            cp16(dst, src);
        }
    }
    kv_issue(sb, b, h, 0, 0, tid);
    CP_COMMIT();
    CP_WAIT0();
    __syncthreads();

    const uint32_t qaddr_base =
        sb + (uint32_t)(Q_OFF + (w * 16 + l15) * FPK + (lane >> 4) * 8) * 2;
    uint32_t qh[4][4];
#pragma unroll
    for (int t = 0; t < 4; t++)
        LDSM_X4(qh[t][0], qh[t][1], qh[t][2], qh[t][3], qaddr_base + (uint32_t)(t * 32));

    float o[8][4];
#pragma unroll
    for (int j = 0; j < 8; j++)
#pragma unroll
        for (int e = 0; e < 4; e++) o[j][e] = 0.0f;
    float m0 = -INFINITY, m1 = -INFINITY, ls0 = 0.0f, ls1 = 0.0f;

    for (int kt = 0; kt < 32; kt++) {
        CP_WAIT0();          // kv(kt) landed locally
        __syncthreads();     // visible to all; previous compute done
        if (kt + 1 < 32) {
            kv_issue(sb, b, h, kt + 1, (kt + 1) & 1, tid);
            CP_COMMIT();
        }
        const uint32_t bufb = sb + (uint32_t)((kt & 1) * KV_BUF) * 2;

        // ---- S = Q K^T (2-term: (Qh+Ql)*Kh) ----
        float s[8][4];
#pragma unroll
        for (int j = 0; j < 8; j++)
#pragma unroll
            for (int e = 0; e < 4; e++) s[j][e] = 0.0f;
#pragma unroll
        for (int t = 0; t < 4; t++) {
            uint32_t ql_t[4];
            LDSM_X4(ql_t[0], ql_t[1], ql_t[2], ql_t[3],
                    qaddr_base + (uint32_t)(t * 32) + Q_TILE * 2);
#pragma unroll
            for (int jp = 0; jp < 4; jp++) {
                uint32_t ka = bufb + (uint32_t)(
                    (8 * (2 * jp + (lane >> 4)) + (lane & 7)) * FPK
                    + t * 16 + ((lane >> 3) & 1) * 8) * 2;
                uint32_t h0, h1, h2, h3;
                LDSM_X4(h0, h1, h2, h3, ka);
                MMA16816(s[2 * jp],     qh[t], h0, h1);
                MMA16816(s[2 * jp],     ql_t,  h0, h1);
                MMA16816(s[2 * jp + 1], qh[t], h2, h3);
                MMA16816(s[2 * jp + 1], ql_t,  h2, h3);
            }
        }

        // ---- online softmax in registers ----
        float mx0 = s[0][0], mx1 = s[0][2];
#pragma unroll
        for (int j = 0; j < 8; j++) {
            mx0 = fmaxf(mx0, fmaxf(s[j][0], s[j][1]));
            mx1 = fmaxf(mx1, fmaxf(s[j][2], s[j][3]));
        }
        mx0 = fmaxf(mx0, __shfl_xor_sync(0xffffffffu, mx0, 1));
        mx0 = fmaxf(mx0, __shfl_xor_sync(0xffffffffu, mx0, 2));
        mx1 = fmaxf(mx1, __shfl_xor_sync(0xffffffffu, mx1, 1));
        mx1 = fmaxf(mx1, __shfl_xor_sync(0xffffffffu, mx1, 2));
        float m0n = fmaxf(m0, mx0), m1n = fmaxf(m1, mx1);
        float a0 = __expf(m0 - m0n), a1 = __expf(m1 - m1n);
        float sum0 = 0.0f, sum1 = 0.0f;
#pragma unroll
        for (int j = 0; j < 8; j++) {
            s[j][0] = __expf(s[j][0] - m0n); sum0 += s[j][0];
            s[j][1] = __expf(s[j][1] - m0n); sum0 += s[j][1];
            s[j][2] = __expf(s[j][2] - m1n); sum1 += s[j][2];
            s[j][3] = __expf(s[j][3] - m1n); sum1 += s[j][3];
        }
        sum0 += __shfl_xor_sync(0xffffffffu, sum0, 1);
        sum0 += __shfl_xor_sync(0xffffffffu, sum0, 2);
        sum1 += __shfl_xor_sync(0xffffffffu, sum1, 1);
        sum1 += __shfl_xor_sync(0xffffffffu, sum1, 2);
        ls0 = ls0 * a0 + sum0; ls1 = ls1 * a1 + sum1;
        m0 = m0n; m1 = m1n;

        uint32_t pa[4][4];
#pragma unroll
        for (int t = 0; t < 4; t++) {
            pa[t][0] = pk2(s[2 * t][0],     s[2 * t][1]);
            pa[t][1] = pk2(s[2 * t][2],     s[2 * t][3]);
            pa[t][2] = pk2(s[2 * t + 1][0], s[2 * t + 1][1]);
            pa[t][3] = pk2(s[2 * t + 1][2], s[2 * t + 1][3]);
        }
#pragma unroll
        for (int j = 0; j < 8; j++) {
            o[j][0] *= a0; o[j][1] *= a0;
            o[j][2] *= a1; o[j][3] *= a1;
        }

        // ---- O += P V (1-term: V hi only) ----
#pragma unroll
        for (int t = 0; t < 4; t++) {
#pragma unroll
            for (int jp = 0; jp < 4; jp++) {
                uint32_t va = bufb + (uint32_t)(KV_TILE
                                + (16 * t + l15) * FPK
                                + 8 * (2 * jp + (lane >> 4))) * 2;
                uint32_t v0, v1, v2, v3;
                LDSM_X4T(v0, v1, v2, v3, va);
                MMA16816(o[2 * jp],     pa[t], v0, v1);
                MMA16816(o[2 * jp + 1], pa[t], v2, v3);
            }
        }
    }

    // ---- epilogue: normalize, write fp16 hi only ----
    {
        float inv0 = 1.0f / ls0, inv1 = 1.0f / ls1;
        size_t row0 = (size_t)(b * NN + q0 + w * 16 + g);
        size_t row1 = row0 + 8;
        int col = h * 64 + 2 * tg;
#pragma unroll
        for (int j = 0; j < 8; j++) {
            size_t i0 = row0 * 1024 + col + 8 * j;
            size_t i1 = row1 * 1024 + col + 8 * j;
            *(__half2*)(g_ath + i0) = __halves2half2(
                __float2half_rn(o[j][0] * inv0), __float2half_rn(o[j][1] * inv0));
            *(__half2*)(g_ath + i1) = __halves2half2(
                __float2half_rn(o[j][2] * inv1), __float2half_rn(o[j][3] * inv1));
        }
    }
}

// ---------------------------------------------------------------------------
extern "C" void kernel_launch(void* const* d_in, const int* in_sizes, int n_in,
                              void* d_out, int out_size)
{
    const float* x      = (const float*)d_in[0];
    const float* w_qkv  = (const float*)d_in[1];
    const float* w_proj = (const float*)d_in[2];
    const float* b_proj = (const float*)d_in[3];
    float* out = (float*)d_out;

    void *xh, *wqh, *wql, *wph, *wpl, *qh, *ql, *ath;
    cudaGetSymbolAddress(&xh, g_xh);
    cudaGetSymbolAddress(&wqh, g_wqh); cudaGetSymbolAddress(&wql, g_wql);
    cudaGetSymbolAddress(&wph, g_wph); cudaGetSymbolAddress(&wpl, g_wpl);
    cudaGetSymbolAddress(&qh, g_qkvh); cudaGetSymbolAddress(&ql, g_qkvl);
    cudaGetSymbolAddress(&ath, g_ath);

    cudaFuncSetAttribute(gemm_h<1>, cudaFuncAttributeMaxDynamicSharedMemorySize, G_SMEM);
    cudaFuncSetAttribute(gemm_h<0>, cudaFuncAttributeMaxDynamicSharedMemorySize, G_SMEM);
    cudaFuncSetAttribute(flash_r, cudaFuncAttributeMaxDynamicSharedMemorySize, F_SMEM);

    splitall<<<8192, 256>>>(x, w_qkv, w_proj);

    // 1) qkv = x @ w_qkv (2-term: xh*(wh+wl)); q cols pre-scaled, q lo kept
    gemm_h<0><<<dim3(24, 32), 256, G_SMEM>>>(
        (const __half*)xh, (const __half*)xh, (const __half*)wqh, (const __half*)wql,
        nullptr, nullptr, (__half*)qh, (__half*)ql, 4096, 3072, 1024, 0);
    // 2) flash attention -> g_ath (hi only)
    flash_r<<<dim3(16, 32), 256, F_SMEM>>>();
    // 3) out = attn @ w_proj + b_proj (2-term)
    gemm_h<0><<<dim3(8, 32), 256, G_SMEM>>>(
        (const __half*)ath, (const __half*)ath, (const __half*)wph, (const __half*)wpl,
        out, b_proj, nullptr, nullptr, 4096, 1024, 1024, 1);
}